// round 15
// baseline (speedup 1.0000x reference)
#include <cuda_runtime.h>
#include <cuda_fp16.h>
#include <stdint.h>

#define N_NODES 50000
#define N_EDGES 800000
#define DIM 128
#define KPI 0.62831853071795865f
#define FULL 0xffffffffu
#define QNB 32
#define QPITCH 136
#define QP_SMEM ((128 * QPITCH + 2 * QNB * QPITCH) * 4)
#define OPITCH 136
#define KO_SMEM ((128 * OPITCH + 2 * 32 * OPITCH + 256) * 4)

// ---- scratch ----
__device__ __half2 g_Ph[(size_t)N_NODES * 512];  // [n][h][64xhalf2], pre-scaled by 0.25
__device__ float g_c[N_NODES * 8];               // (q.b_K)*0.25
__device__ float g_WKT[DIM * DIM];
__device__ uint2 g_U2[(size_t)N_NODES * 256];    // Unorm fp16: [n][h][32xuint2(4 half)]
__device__ float g_T[N_NODES * 8];               // sum(alpha*phi) per (n,h)
__device__ int   g_counts[N_NODES];
__device__ int   g_offsets[N_NODES + 1];
__device__ int   g_cursor[N_NODES];
__device__ int2  g_pe[N_EDGES];                  // (edge, phi bits) CSR order

__device__ __forceinline__ uint32_t f2tf(float f) {
    uint32_t o;
    asm("cvt.rna.tf32.f32 %0, %1;" : "=r"(o) : "f"(f));
    return o;
}
__device__ __forceinline__ void mma_tf32(float c[4], uint32_t a0, uint32_t a1,
                                         uint32_t a2, uint32_t a3,
                                         uint32_t b0, uint32_t b1) {
    asm volatile(
        "mma.sync.aligned.m16n8k8.row.col.f32.tf32.tf32.f32 "
        "{%0,%1,%2,%3}, {%4,%5,%6,%7}, {%8,%9}, {%0,%1,%2,%3};"
        : "+f"(c[0]), "+f"(c[1]), "+f"(c[2]), "+f"(c[3])
        : "r"(a0), "r"(a1), "r"(a2), "r"(a3), "r"(b0), "r"(b1));
}

// ---- CSR build ----
__global__ void k_zero() {
    int i = blockIdx.x * blockDim.x + threadIdx.x;
    if (i < N_NODES) g_counts[i] = 0;
}
__global__ void k_hist(const int* __restrict__ ei) {
    int e = blockIdx.x * blockDim.x + threadIdx.x;
    if (e < N_EDGES) atomicAdd(&g_counts[ei[N_EDGES + e]], 1);
}
__global__ void k_scan() {
    __shared__ int wsum[32];
    int t = threadIdx.x, lane = t & 31, wid = t >> 5;
    int carry = 0;
    for (int base = 0; base < N_NODES; base += 1024) {
        int i = base + t;
        int v = (i < N_NODES) ? g_counts[i] : 0;
        int x = v;
        #pragma unroll
        for (int o = 1; o < 32; o <<= 1) { int y = __shfl_up_sync(FULL, x, o); if (lane >= o) x += y; }
        if (lane == 31) wsum[wid] = x;
        __syncthreads();
        if (wid == 0) {
            int s = wsum[lane];
            #pragma unroll
            for (int o = 1; o < 32; o <<= 1) { int y = __shfl_up_sync(FULL, s, o); if (lane >= o) s += y; }
            wsum[lane] = s;
        }
        __syncthreads();
        int excl = x - v + (wid ? wsum[wid - 1] : 0);
        if (i < N_NODES) { g_offsets[i] = carry + excl; g_cursor[i] = carry + excl; }
        carry += wsum[31];
        __syncthreads();
    }
    if (t == 0) g_offsets[N_NODES] = carry;
}
__global__ void k_scatter(const int* __restrict__ ei, const float* __restrict__ elen) {
    int e = blockIdx.x * blockDim.x + threadIdx.x;
    if (e < N_EDGES) {
        int j = ei[N_EDGES + e];
        int pos = atomicAdd(&g_cursor[j], 1);
        float phi = fmaf(0.5f, __cosf(elen[e] * KPI), 0.5f);
        g_pe[pos] = make_int2(e, __float_as_int(phi));
    }
}
__global__ void k_wkt(const float* __restrict__ WK) {
    int i = blockIdx.x * blockDim.x + threadIdx.x;
    if (i < DIM * DIM) g_WKT[(i % DIM) * DIM + (i / DIM)] = WK[i];
}

// ---- node precompute on tensor cores (tf32): q = xWQ+bQ; P_h = q_h @ WKT_h ----
__global__ void __launch_bounds__(128) k_qp(
    const float* __restrict__ x, const float* __restrict__ WQ,
    const float* __restrict__ bQ, const float* __restrict__ bK)
{
    extern __shared__ uint32_t sm[];
    uint32_t* s_w = sm;
    uint32_t* s_x = sm + 128 * QPITCH;
    uint32_t* s_q = s_x + QNB * QPITCH;
    int tid = threadIdx.x, lane = tid & 31, wp = tid >> 5;
    int g = lane >> 2, tg = lane & 3;
    int nb0 = blockIdx.x * QNB;
    int wbase = wp * 32;

    #pragma unroll
    for (int it = 0; it < 8; it++) {
        int idx = tid + it * 128;
        int row = idx >> 5, c4 = (idx & 31) * 4;
        int node = nb0 + row;
        float4 v = make_float4(0.f, 0.f, 0.f, 0.f);
        if (node < N_NODES) v = *reinterpret_cast<const float4*>(x + (size_t)node * DIM + c4);
        s_x[row * QPITCH + c4 + 0] = f2tf(v.x);
        s_x[row * QPITCH + c4 + 1] = f2tf(v.y);
        s_x[row * QPITCH + c4 + 2] = f2tf(v.z);
        s_x[row * QPITCH + c4 + 3] = f2tf(v.w);
    }
    #pragma unroll 8
    for (int it = 0; it < 32; it++) {
        int idx = tid + it * 128;
        int row = idx >> 5, c4 = (idx & 31) * 4;
        float4 v = *reinterpret_cast<const float4*>(WQ + row * DIM + c4);
        s_w[row * QPITCH + c4 + 0] = f2tf(v.x);
        s_w[row * QPITCH + c4 + 1] = f2tf(v.y);
        s_w[row * QPITCH + c4 + 2] = f2tf(v.z);
        s_w[row * QPITCH + c4 + 3] = f2tf(v.w);
    }
    __syncthreads();

    #pragma unroll
    for (int mt = 0; mt < 2; mt++) {
        float c[4][4];
        #pragma unroll
        for (int nt = 0; nt < 4; nt++) {
            int col = wbase + nt * 8 + 2 * tg;
            c[nt][0] = bQ[col]; c[nt][1] = bQ[col + 1];
            c[nt][2] = c[nt][0]; c[nt][3] = c[nt][1];
        }
        #pragma unroll
        for (int kt = 0; kt < 16; kt++) {
            int ra = (mt * 16 + g) * QPITCH + kt * 8 + tg;
            int rb = (mt * 16 + g + 8) * QPITCH + kt * 8 + tg;
            uint32_t a0 = s_x[ra], a1 = s_x[rb], a2 = s_x[ra + 4], a3 = s_x[rb + 4];
            #pragma unroll
            for (int nt = 0; nt < 4; nt++) {
                int cb = wbase + nt * 8 + g;
                uint32_t b0 = s_w[(kt * 8 + tg) * QPITCH + cb];
                uint32_t b1 = s_w[(kt * 8 + tg + 4) * QPITCH + cb];
                mma_tf32(c[nt], a0, a1, a2, a3, b0, b1);
            }
        }
        #pragma unroll
        for (int nt = 0; nt < 4; nt++) {
            int col = wbase + nt * 8 + 2 * tg;
            s_q[(mt * 16 + g) * QPITCH + col]         = f2tf(c[nt][0]);
            s_q[(mt * 16 + g) * QPITCH + col + 1]     = f2tf(c[nt][1]);
            s_q[(mt * 16 + g + 8) * QPITCH + col]     = f2tf(c[nt][2]);
            s_q[(mt * 16 + g + 8) * QPITCH + col + 1] = f2tf(c[nt][3]);
        }
    }
    __syncthreads();

    #pragma unroll 8
    for (int it = 0; it < 32; it++) {
        int idx = tid + it * 128;
        int row = idx >> 5, c4 = (idx & 31) * 4;
        float4 v = *reinterpret_cast<const float4*>(g_WKT + row * DIM + c4);
        s_w[row * QPITCH + c4 + 0] = f2tf(v.x);
        s_w[row * QPITCH + c4 + 1] = f2tf(v.y);
        s_w[row * QPITCH + c4 + 2] = f2tf(v.z);
        s_w[row * QPITCH + c4 + 3] = f2tf(v.w);
    }
    #pragma unroll
    for (int it = 0; it < 2; it++) {
        int item = tid + it * 128;
        int i = item >> 3, h = item & 7;
        int node = nb0 + i;
        if (node < N_NODES) {
            float cc = 0.f;
            #pragma unroll
            for (int k = 0; k < 16; k++)
                cc = fmaf(__uint_as_float(s_q[i * QPITCH + h * 16 + k]), bK[h * 16 + k], cc);
            g_c[node * 8 + h] = cc * 0.25f;
        }
    }
    __syncthreads();

    #pragma unroll
    for (int mt = 0; mt < 2; mt++) {
        int node0 = nb0 + mt * 16 + g, node1 = node0 + 8;
        #pragma unroll
        for (int h = 0; h < 8; h++) {
            float c[4][4];
            #pragma unroll
            for (int nt = 0; nt < 4; nt++)
                c[nt][0] = c[nt][1] = c[nt][2] = c[nt][3] = 0.f;
            #pragma unroll
            for (int kt = 0; kt < 2; kt++) {
                int qa = (mt * 16 + g) * QPITCH + h * 16 + kt * 8 + tg;
                int qb = (mt * 16 + g + 8) * QPITCH + h * 16 + kt * 8 + tg;
                uint32_t a0 = s_q[qa], a1 = s_q[qb], a2 = s_q[qa + 4], a3 = s_q[qb + 4];
                #pragma unroll
                for (int nt = 0; nt < 4; nt++) {
                    int cb = wbase + nt * 8 + g;
                    uint32_t b0 = s_w[(h * 16 + kt * 8 + tg) * QPITCH + cb];
                    uint32_t b1 = s_w[(h * 16 + kt * 8 + tg + 4) * QPITCH + cb];
                    mma_tf32(c[nt], a0, a1, a2, a3, b0, b1);
                }
            }
            if (node0 < N_NODES) {
                #pragma unroll
                for (int nt = 0; nt < 4; nt++) {
                    int c2 = wp * 16 + nt * 4 + tg;
                    g_Ph[(size_t)node0 * 512 + h * 64 + c2] =
                        __floats2half2_rn(0.25f * c[nt][0], 0.25f * c[nt][1]);
                }
            }
            if (node1 < N_NODES) {
                #pragma unroll
                for (int nt = 0; nt < 4; nt++) {
                    int c2 = wp * 16 + nt * 4 + tg;
                    g_Ph[(size_t)node1 * 512 + h * 64 + c2] =
                        __floats2half2_rn(0.25f * c[nt][2], 0.25f * c[nt][3]);
                }
            }
        }
    }
}

// ---- fused edge pass (warp=node, 4 nodes/block); writes Unorm fp16 + sT ----
__global__ void __launch_bounds__(128, 5) k_edge(const float4* __restrict__ ea4)
{
    int tid = threadIdx.x, w = tid >> 5, l = tid & 31;
    int n = blockIdx.x * 4 + w;

    float4 P4[8];
    {
        const uint2* gp = reinterpret_cast<const uint2*>(g_Ph + (size_t)n * 512);
        #pragma unroll
        for (int h = 0; h < 8; h++) {
            uint2 v = gp[h * 32 + l];
            float2 f01 = __half22float2(*reinterpret_cast<__half2*>(&v.x));
            float2 f23 = __half22float2(*reinterpret_cast<__half2*>(&v.y));
            P4[h] = make_float4(f01.x, f01.y, f23.x, f23.y);
        }
    }
    float ch = g_c[n * 8 + (l >> 2)];

    float4 U[8];
    #pragma unroll
    for (int h = 0; h < 8; h++) U[h] = make_float4(0.f, 0.f, 0.f, 0.f);
    float ssum = 0.f, tsum = 0.f;
    bool b4 = (l & 16), b3 = (l & 8), b2 = (l & 4);

    int beg = g_offsets[n], end = g_offsets[n + 1];
    int2 pe0 = make_int2(0, 0), pe1 = pe0, pe2 = pe0;
    float4 a0 = make_float4(0.f, 0.f, 0.f, 0.f), a1 = a0, a2 = a0;
    if (beg < end)     { pe0 = g_pe[beg];     a0 = __ldcs(&ea4[(size_t)pe0.x * 32 + l]); }
    if (beg + 1 < end) { pe1 = g_pe[beg + 1]; a1 = __ldcs(&ea4[(size_t)pe1.x * 32 + l]); }
    if (beg + 2 < end) { pe2 = g_pe[beg + 2]; a2 = __ldcs(&ea4[(size_t)pe2.x * 32 + l]); }

    for (int i = beg; i < end; i++) {
        float4 ac = a0; float phi = __int_as_float(pe0.y);
        pe0 = pe1; a0 = a1;
        pe1 = pe2; a1 = a2;
        if (i + 3 < end) { pe2 = g_pe[i + 3]; a2 = __ldcs(&ea4[(size_t)pe2.x * 32 + l]); }

        float p[8];
        #pragma unroll
        for (int h = 0; h < 8; h++)
            p[h] = fmaf(ac.x, P4[h].x, fmaf(ac.y, P4[h].y, fmaf(ac.z, P4[h].z, ac.w * P4[h].w)));

        float r0, r1, r2, r3;
        {
            float t0 = b4 ? p[0] : p[4], t1 = b4 ? p[1] : p[5];
            float t2 = b4 ? p[2] : p[6], t3 = b4 ? p[3] : p[7];
            r0 = (b4 ? p[4] : p[0]) + __shfl_xor_sync(FULL, t0, 16);
            r1 = (b4 ? p[5] : p[1]) + __shfl_xor_sync(FULL, t1, 16);
            r2 = (b4 ? p[6] : p[2]) + __shfl_xor_sync(FULL, t2, 16);
            r3 = (b4 ? p[7] : p[3]) + __shfl_xor_sync(FULL, t3, 16);
        }
        float s0, s1;
        {
            float t0 = b3 ? r0 : r2, t1 = b3 ? r1 : r3;
            s0 = (b3 ? r2 : r0) + __shfl_xor_sync(FULL, t0, 8);
            s1 = (b3 ? r3 : r1) + __shfl_xor_sync(FULL, t1, 8);
        }
        float s;
        {
            float t0 = b2 ? s0 : s1;
            s = (b2 ? s1 : s0) + __shfl_xor_sync(FULL, t0, 4);
        }
        s += __shfl_xor_sync(FULL, s, 2);
        s += __shfl_xor_sync(FULL, s, 1);

        float ex = __expf(s + ch);
        float wh = ex * phi;
        ssum += ex; tsum += wh;

        #pragma unroll
        for (int h = 0; h < 8; h++) {
            float whh = __shfl_sync(FULL, wh, 4 * h);
            U[h].x = fmaf(whh, ac.x, U[h].x);
            U[h].y = fmaf(whh, ac.y, U[h].y);
            U[h].z = fmaf(whh, ac.z, U[h].z);
            U[h].w = fmaf(whh, ac.w, U[h].w);
        }
    }

    float invm = (ssum > 0.f) ? (1.f / ssum) : 0.f;
    if ((l & 3) == 0) g_T[n * 8 + (l >> 2)] = tsum * invm;
    #pragma unroll
    for (int h = 0; h < 8; h++) {
        float ivh = __shfl_sync(FULL, invm, 4 * h);
        __half2 ha = __floats2half2_rn(U[h].x * ivh, U[h].y * ivh);
        __half2 hb = __floats2half2_rn(U[h].z * ivh, U[h].w * ivh);
        uint2 pk;
        pk.x = *reinterpret_cast<uint32_t*>(&ha);
        pk.y = *reinterpret_cast<uint32_t*>(&hb);
        g_U2[(size_t)n * 256 + h * 32 + l] = pk;
    }
}

// ---- epilogue on tensor cores: out = blockdiag(U @ WV_h) @ WO + sT*bV@WO + bO ----
__global__ void __launch_bounds__(128) k_out(
    const float* __restrict__ WV, const float* __restrict__ bV,
    const float* __restrict__ WO, const float* __restrict__ bO,
    float* __restrict__ out)
{
    extern __shared__ uint32_t osm[];
    uint32_t* s_w  = osm;                       // [128][OPITCH] WV then WO (tf32)
    uint32_t* s_u  = osm + 128 * OPITCH;        // [32][OPITCH]
    uint32_t* s_no = s_u + 32 * OPITCH;         // [32][OPITCH]
    float*    s_t  = (float*)(s_no + 32 * OPITCH);  // [32][8] = 256 floats
    int tid = threadIdx.x, lane = tid & 31, wp = tid >> 5;
    int g = lane >> 2, tg = lane & 3;
    int nb0 = blockIdx.x * 32;

    // stage WV + sT
    #pragma unroll 8
    for (int it = 0; it < 32; it++) {
        int idx = tid + it * 128;
        int row = idx >> 5, c4 = (idx & 31) * 4;
        float4 v = *reinterpret_cast<const float4*>(WV + row * DIM + c4);
        s_w[row * OPITCH + c4 + 0] = f2tf(v.x);
        s_w[row * OPITCH + c4 + 1] = f2tf(v.y);
        s_w[row * OPITCH + c4 + 2] = f2tf(v.z);
        s_w[row * OPITCH + c4 + 3] = f2tf(v.w);
    }
    #pragma unroll
    for (int it = 0; it < 2; it++) {
        int idx = tid + it * 128;
        int i = idx >> 3, h = idx & 7;
        int node = nb0 + i;
        s_t[idx] = (node < N_NODES) ? g_T[node * 8 + h] : 0.f;
    }
    __syncthreads();

    int mt1 = wp >> 1, nt1 = wp & 1;
    #pragma unroll 1
    for (int h = 0; h < 8; h++) {
        // stage U_h (fp16 -> tf32)
        #pragma unroll
        for (int it = 0; it < 8; it++) {
            int idx = tid + it * 128;
            int row = idx >> 5, j = idx & 31;
            int node = nb0 + row;
            uint2 uv = make_uint2(0u, 0u);
            if (node < N_NODES) uv = g_U2[(size_t)node * 256 + h * 32 + j];
            float2 f01 = __half22float2(*reinterpret_cast<__half2*>(&uv.x));
            float2 f23 = __half22float2(*reinterpret_cast<__half2*>(&uv.y));
            s_u[row * OPITCH + 4 * j + 0] = f2tf(f01.x);
            s_u[row * OPITCH + 4 * j + 1] = f2tf(f01.y);
            s_u[row * OPITCH + 4 * j + 2] = f2tf(f23.x);
            s_u[row * OPITCH + 4 * j + 3] = f2tf(f23.y);
        }
        __syncthreads();

        // GEMM1 tile for this warp: rows mt1*16.., cols h*16+nt1*8..
        int colb = h * 16 + nt1 * 8;
        float c[4];
        {
            float bv0 = __ldg(bV + colb + 2 * tg), bv1 = __ldg(bV + colb + 2 * tg + 1);
            float t0 = s_t[(mt1 * 16 + g) * 8 + h], t1 = s_t[(mt1 * 16 + g + 8) * 8 + h];
            c[0] = t0 * bv0; c[1] = t0 * bv1; c[2] = t1 * bv0; c[3] = t1 * bv1;
        }
        #pragma unroll
        for (int kt = 0; kt < 16; kt++) {
            int ra = (mt1 * 16 + g) * OPITCH + kt * 8 + tg;
            int rb = (mt1 * 16 + g + 8) * OPITCH + kt * 8 + tg;
            uint32_t b0 = s_w[(kt * 8 + tg) * OPITCH + colb + g];
            uint32_t b1 = s_w[(kt * 8 + tg + 4) * OPITCH + colb + g];
            mma_tf32(c, s_u[ra], s_u[rb], s_u[ra + 4], s_u[rb + 4], b0, b1);
        }
        s_no[(mt1 * 16 + g) * OPITCH + colb + 2 * tg]         = f2tf(c[0]);
        s_no[(mt1 * 16 + g) * OPITCH + colb + 2 * tg + 1]     = f2tf(c[1]);
        s_no[(mt1 * 16 + g + 8) * OPITCH + colb + 2 * tg]     = f2tf(c[2]);
        s_no[(mt1 * 16 + g + 8) * OPITCH + colb + 2 * tg + 1] = f2tf(c[3]);
        __syncthreads();
    }

    // stage WO over s_w
    #pragma unroll 8
    for (int it = 0; it < 32; it++) {
        int idx = tid + it * 128;
        int row = idx >> 5, c4 = (idx & 31) * 4;
        float4 v = *reinterpret_cast<const float4*>(WO + row * DIM + c4);
        s_w[row * OPITCH + c4 + 0] = f2tf(v.x);
        s_w[row * OPITCH + c4 + 1] = f2tf(v.y);
        s_w[row * OPITCH + c4 + 2] = f2tf(v.z);
        s_w[row * OPITCH + c4 + 3] = f2tf(v.w);
    }
    __syncthreads();

    // GEMM2: out[32,128] = s_no @ WO + bO
    #pragma unroll
    for (int mt = 0; mt < 2; mt++) {
        #pragma unroll
        for (int nn = 0; nn < 4; nn++) {
            int nt = wp * 4 + nn;
            int colb = nt * 8;
            float c[4];
            float bo0 = __ldg(bO + colb + 2 * tg), bo1 = __ldg(bO + colb + 2 * tg + 1);
            c[0] = bo0; c[1] = bo1; c[2] = bo0; c[3] = bo1;
            #pragma unroll
            for (int kt = 0; kt < 16; kt++) {
                int ra = (mt * 16 + g) * OPITCH + kt * 8 + tg;
                int rb = (mt * 16 + g + 8) * OPITCH + kt * 8 + tg;
                uint32_t b0 = s_w[(kt * 8 + tg) * OPITCH + colb + g];
                uint32_t b1 = s_w[(kt * 8 + tg + 4) * OPITCH + colb + g];
                mma_tf32(c, s_no[ra], s_no[rb], s_no[ra + 4], s_no[rb + 4], b0, b1);
            }
            int n0 = nb0 + mt * 16 + g, n1 = n0 + 8;
            if (n0 < N_NODES) {
                out[(size_t)n0 * DIM + colb + 2 * tg]     = c[0];
                out[(size_t)n0 * DIM + colb + 2 * tg + 1] = c[1];
            }
            if (n1 < N_NODES) {
                out[(size_t)n1 * DIM + colb + 2 * tg]     = c[2];
                out[(size_t)n1 * DIM + colb + 2 * tg + 1] = c[3];
            }
        }
    }
}

extern "C" void kernel_launch(void* const* d_in, const int* in_sizes, int n_in,
                              void* d_out, int out_size) {
    const float* x    = (const float*)d_in[0];
    const int*   ei   = (const int*)  d_in[1];
    const float* ea   = (const float*)d_in[2];
    const float* elen = (const float*)d_in[3];
    const float* WQ   = (const float*)d_in[4];
    const float* bQ   = (const float*)d_in[5];
    const float* WK   = (const float*)d_in[6];
    const float* bK   = (const float*)d_in[7];
    const float* WV   = (const float*)d_in[8];
    const float* bV   = (const float*)d_in[9];
    const float* WO   = (const float*)d_in[10];
    const float* bO   = (const float*)d_in[11];
    float* out = (float*)d_out;

    static bool attr_set = false;
    if (!attr_set) {
        cudaFuncSetAttribute(k_qp, cudaFuncAttributeMaxDynamicSharedMemorySize, QP_SMEM);
        cudaFuncSetAttribute(k_out, cudaFuncAttributeMaxDynamicSharedMemorySize, KO_SMEM);
        attr_set = true;
    }

    k_zero<<<(N_NODES + 255) / 256, 256>>>();
    k_hist<<<(N_EDGES + 255) / 256, 256>>>(ei);
    k_scan<<<1, 1024>>>();
    k_scatter<<<(N_EDGES + 255) / 256, 256>>>(ei, elen);
    k_wkt<<<(DIM * DIM + 255) / 256, 256>>>(WK);
    k_qp<<<(N_NODES + QNB - 1) / QNB, 128, QP_SMEM>>>(x, WQ, bQ, bK);
    k_edge<<<N_NODES / 4, 128>>>((const float4*)ea);
    k_out<<<(N_NODES + 31) / 32, 128, KO_SMEM>>>(WV, bV, WO, bO, out);
}

// round 16
// speedup vs baseline: 1.1650x; 1.1650x over previous
#include <cuda_runtime.h>
#include <cuda_fp16.h>
#include <stdint.h>

#define N_NODES 50000
#define N_EDGES 800000
#define DIM 128
#define KPI 0.62831853071795865f
#define FULL 0xffffffffu
#define QNB 32
#define QPITCH 136
#define QP_SMEM ((128 * QPITCH + 2 * QNB * QPITCH) * 4)

// ---- scratch ----
__device__ __half2 g_Ph[(size_t)N_NODES * 512];  // [n][h][64xhalf2], pre-scaled by 0.25
__device__ float g_c[N_NODES * 8];               // (q.b_K)*0.25
__device__ float g_WKT[DIM * DIM];
__device__ int   g_counts[N_NODES];
__device__ int   g_offsets[N_NODES + 1];
__device__ int   g_cursor[N_NODES];
__device__ int2  g_pe[N_EDGES];                  // (edge, phi bits) CSR order

__device__ __forceinline__ uint32_t f2tf(float f) {
    uint32_t o;
    asm("cvt.rna.tf32.f32 %0, %1;" : "=r"(o) : "f"(f));
    return o;
}
__device__ __forceinline__ void mma_tf32(float c[4], uint32_t a0, uint32_t a1,
                                         uint32_t a2, uint32_t a3,
                                         uint32_t b0, uint32_t b1) {
    asm volatile(
        "mma.sync.aligned.m16n8k8.row.col.f32.tf32.tf32.f32 "
        "{%0,%1,%2,%3}, {%4,%5,%6,%7}, {%8,%9}, {%0,%1,%2,%3};"
        : "+f"(c[0]), "+f"(c[1]), "+f"(c[2]), "+f"(c[3])
        : "r"(a0), "r"(a1), "r"(a2), "r"(a3), "r"(b0), "r"(b1));
}

// ---- CSR build ----
__global__ void k_zero() {
    int i = blockIdx.x * blockDim.x + threadIdx.x;
    if (i < N_NODES) g_counts[i] = 0;
}
__global__ void k_hist(const int* __restrict__ ei) {
    int e = blockIdx.x * blockDim.x + threadIdx.x;
    if (e < N_EDGES) atomicAdd(&g_counts[ei[N_EDGES + e]], 1);
}
__global__ void k_scan() {
    __shared__ int wsum[32];
    int t = threadIdx.x, lane = t & 31, wid = t >> 5;
    int carry = 0;
    for (int base = 0; base < N_NODES; base += 1024) {
        int i = base + t;
        int v = (i < N_NODES) ? g_counts[i] : 0;
        int x = v;
        #pragma unroll
        for (int o = 1; o < 32; o <<= 1) { int y = __shfl_up_sync(FULL, x, o); if (lane >= o) x += y; }
        if (lane == 31) wsum[wid] = x;
        __syncthreads();
        if (wid == 0) {
            int s = wsum[lane];
            #pragma unroll
            for (int o = 1; o < 32; o <<= 1) { int y = __shfl_up_sync(FULL, s, o); if (lane >= o) s += y; }
            wsum[lane] = s;
        }
        __syncthreads();
        int excl = x - v + (wid ? wsum[wid - 1] : 0);
        if (i < N_NODES) { g_offsets[i] = carry + excl; g_cursor[i] = carry + excl; }
        carry += wsum[31];
        __syncthreads();
    }
    if (t == 0) g_offsets[N_NODES] = carry;
}
__global__ void k_scatter(const int* __restrict__ ei, const float* __restrict__ elen) {
    int e = blockIdx.x * blockDim.x + threadIdx.x;
    if (e < N_EDGES) {
        int j = ei[N_EDGES + e];
        int pos = atomicAdd(&g_cursor[j], 1);
        float phi = fmaf(0.5f, __cosf(elen[e] * KPI), 0.5f);
        g_pe[pos] = make_int2(e, __float_as_int(phi));
    }
}
__global__ void k_wkt(const float* __restrict__ WK) {
    int i = blockIdx.x * blockDim.x + threadIdx.x;
    if (i < DIM * DIM) g_WKT[(i % DIM) * DIM + (i / DIM)] = WK[i];
}

// ---- node precompute on tensor cores (tf32): q = xWQ+bQ; P_h = q_h @ WKT_h ----
__global__ void __launch_bounds__(128) k_qp(
    const float* __restrict__ x, const float* __restrict__ WQ,
    const float* __restrict__ bQ, const float* __restrict__ bK)
{
    extern __shared__ uint32_t sm[];
    uint32_t* s_w = sm;
    uint32_t* s_x = sm + 128 * QPITCH;
    uint32_t* s_q = s_x + QNB * QPITCH;
    int tid = threadIdx.x, lane = tid & 31, wp = tid >> 5;
    int g = lane >> 2, tg = lane & 3;
    int nb0 = blockIdx.x * QNB;
    int wbase = wp * 32;

    #pragma unroll
    for (int it = 0; it < 8; it++) {
        int idx = tid + it * 128;
        int row = idx >> 5, c4 = (idx & 31) * 4;
        int node = nb0 + row;
        float4 v = make_float4(0.f, 0.f, 0.f, 0.f);
        if (node < N_NODES) v = *reinterpret_cast<const float4*>(x + (size_t)node * DIM + c4);
        s_x[row * QPITCH + c4 + 0] = f2tf(v.x);
        s_x[row * QPITCH + c4 + 1] = f2tf(v.y);
        s_x[row * QPITCH + c4 + 2] = f2tf(v.z);
        s_x[row * QPITCH + c4 + 3] = f2tf(v.w);
    }
    #pragma unroll 8
    for (int it = 0; it < 32; it++) {
        int idx = tid + it * 128;
        int row = idx >> 5, c4 = (idx & 31) * 4;
        float4 v = *reinterpret_cast<const float4*>(WQ + row * DIM + c4);
        s_w[row * QPITCH + c4 + 0] = f2tf(v.x);
        s_w[row * QPITCH + c4 + 1] = f2tf(v.y);
        s_w[row * QPITCH + c4 + 2] = f2tf(v.z);
        s_w[row * QPITCH + c4 + 3] = f2tf(v.w);
    }
    __syncthreads();

    #pragma unroll
    for (int mt = 0; mt < 2; mt++) {
        float c[4][4];
        #pragma unroll
        for (int nt = 0; nt < 4; nt++) {
            int col = wbase + nt * 8 + 2 * tg;
            c[nt][0] = bQ[col]; c[nt][1] = bQ[col + 1];
            c[nt][2] = c[nt][0]; c[nt][3] = c[nt][1];
        }
        #pragma unroll
        for (int kt = 0; kt < 16; kt++) {
            int ra = (mt * 16 + g) * QPITCH + kt * 8 + tg;
            int rb = (mt * 16 + g + 8) * QPITCH + kt * 8 + tg;
            uint32_t a0 = s_x[ra], a1 = s_x[rb], a2 = s_x[ra + 4], a3 = s_x[rb + 4];
            #pragma unroll
            for (int nt = 0; nt < 4; nt++) {
                int cb = wbase + nt * 8 + g;
                uint32_t b0 = s_w[(kt * 8 + tg) * QPITCH + cb];
                uint32_t b1 = s_w[(kt * 8 + tg + 4) * QPITCH + cb];
                mma_tf32(c[nt], a0, a1, a2, a3, b0, b1);
            }
        }
        #pragma unroll
        for (int nt = 0; nt < 4; nt++) {
            int col = wbase + nt * 8 + 2 * tg;
            s_q[(mt * 16 + g) * QPITCH + col]         = f2tf(c[nt][0]);
            s_q[(mt * 16 + g) * QPITCH + col + 1]     = f2tf(c[nt][1]);
            s_q[(mt * 16 + g + 8) * QPITCH + col]     = f2tf(c[nt][2]);
            s_q[(mt * 16 + g + 8) * QPITCH + col + 1] = f2tf(c[nt][3]);
        }
    }
    __syncthreads();

    #pragma unroll 8
    for (int it = 0; it < 32; it++) {
        int idx = tid + it * 128;
        int row = idx >> 5, c4 = (idx & 31) * 4;
        float4 v = *reinterpret_cast<const float4*>(g_WKT + row * DIM + c4);
        s_w[row * QPITCH + c4 + 0] = f2tf(v.x);
        s_w[row * QPITCH + c4 + 1] = f2tf(v.y);
        s_w[row * QPITCH + c4 + 2] = f2tf(v.z);
        s_w[row * QPITCH + c4 + 3] = f2tf(v.w);
    }
    #pragma unroll
    for (int it = 0; it < 2; it++) {
        int item = tid + it * 128;
        int i = item >> 3, h = item & 7;
        int node = nb0 + i;
        if (node < N_NODES) {
            float cc = 0.f;
            #pragma unroll
            for (int k = 0; k < 16; k++)
                cc = fmaf(__uint_as_float(s_q[i * QPITCH + h * 16 + k]), bK[h * 16 + k], cc);
            g_c[node * 8 + h] = cc * 0.25f;
        }
    }
    __syncthreads();

    #pragma unroll
    for (int mt = 0; mt < 2; mt++) {
        int node0 = nb0 + mt * 16 + g, node1 = node0 + 8;
        #pragma unroll
        for (int h = 0; h < 8; h++) {
            float c[4][4];
            #pragma unroll
            for (int nt = 0; nt < 4; nt++)
                c[nt][0] = c[nt][1] = c[nt][2] = c[nt][3] = 0.f;
            #pragma unroll
            for (int kt = 0; kt < 2; kt++) {
                int qa = (mt * 16 + g) * QPITCH + h * 16 + kt * 8 + tg;
                int qb = (mt * 16 + g + 8) * QPITCH + h * 16 + kt * 8 + tg;
                uint32_t a0 = s_q[qa], a1 = s_q[qb], a2 = s_q[qa + 4], a3 = s_q[qb + 4];
                #pragma unroll
                for (int nt = 0; nt < 4; nt++) {
                    int cb = wbase + nt * 8 + g;
                    uint32_t b0 = s_w[(h * 16 + kt * 8 + tg) * QPITCH + cb];
                    uint32_t b1 = s_w[(h * 16 + kt * 8 + tg + 4) * QPITCH + cb];
                    mma_tf32(c[nt], a0, a1, a2, a3, b0, b1);
                }
            }
            if (node0 < N_NODES) {
                #pragma unroll
                for (int nt = 0; nt < 4; nt++) {
                    int c2 = wp * 16 + nt * 4 + tg;
                    g_Ph[(size_t)node0 * 512 + h * 64 + c2] =
                        __floats2half2_rn(0.25f * c[nt][0], 0.25f * c[nt][1]);
                }
            }
            if (node1 < N_NODES) {
                #pragma unroll
                for (int nt = 0; nt < 4; nt++) {
                    int c2 = wp * 16 + nt * 4 + tg;
                    g_Ph[(size_t)node1 * 512 + h * 64 + c2] =
                        __floats2half2_rn(0.25f * c[nt][2], 0.25f * c[nt][3]);
                }
            }
        }
    }
}

// ---- fused edge pass (warp=node, 4 nodes/block) + cooperative epilogue ----
__global__ void __launch_bounds__(128, 5) k_edge(
    const float4* __restrict__ ea4,
    const float* __restrict__ WV, const float* __restrict__ bV,
    const float* __restrict__ WO, const float* __restrict__ bO,
    float* __restrict__ out)
{
    __shared__ float sU[4][8][DIM];
    __shared__ float sT[4][8];
    __shared__ float sno[4][DIM];
    int tid = threadIdx.x, w = tid >> 5, l = tid & 31;
    int n = blockIdx.x * 4 + w;

    float4 P4[8];
    {
        const uint2* gp = reinterpret_cast<const uint2*>(g_Ph + (size_t)n * 512);
        #pragma unroll
        for (int h = 0; h < 8; h++) {
            uint2 v = gp[h * 32 + l];
            float2 f01 = __half22float2(*reinterpret_cast<__half2*>(&v.x));
            float2 f23 = __half22float2(*reinterpret_cast<__half2*>(&v.y));
            P4[h] = make_float4(f01.x, f01.y, f23.x, f23.y);
        }
    }
    float ch = g_c[n * 8 + (l >> 2)];

    float4 U[8];
    #pragma unroll
    for (int h = 0; h < 8; h++) U[h] = make_float4(0.f, 0.f, 0.f, 0.f);
    float ssum = 0.f, tsum = 0.f;
    bool b4 = (l & 16), b3 = (l & 8), b2 = (l & 4);

    int beg = g_offsets[n], end = g_offsets[n + 1];
    int2 pe0 = make_int2(0, 0), pe1 = pe0, pe2 = pe0;
    float4 a0 = make_float4(0.f, 0.f, 0.f, 0.f), a1 = a0, a2 = a0;
    if (beg < end)     { pe0 = g_pe[beg];     a0 = __ldcs(&ea4[(size_t)pe0.x * 32 + l]); }
    if (beg + 1 < end) { pe1 = g_pe[beg + 1]; a1 = __ldcs(&ea4[(size_t)pe1.x * 32 + l]); }
    if (beg + 2 < end) { pe2 = g_pe[beg + 2]; a2 = __ldcs(&ea4[(size_t)pe2.x * 32 + l]); }

    for (int i = beg; i < end; i++) {
        float4 ac = a0; float phi = __int_as_float(pe0.y);
        pe0 = pe1; a0 = a1;
        pe1 = pe2; a1 = a2;
        if (i + 3 < end) { pe2 = g_pe[i + 3]; a2 = __ldcs(&ea4[(size_t)pe2.x * 32 + l]); }

        float p[8];
        #pragma unroll
        for (int h = 0; h < 8; h++)
            p[h] = fmaf(ac.x, P4[h].x, fmaf(ac.y, P4[h].y, fmaf(ac.z, P4[h].z, ac.w * P4[h].w)));

        float r0, r1, r2, r3;
        {
            float t0 = b4 ? p[0] : p[4], t1 = b4 ? p[1] : p[5];
            float t2 = b4 ? p[2] : p[6], t3 = b4 ? p[3] : p[7];
            r0 = (b4 ? p[4] : p[0]) + __shfl_xor_sync(FULL, t0, 16);
            r1 = (b4 ? p[5] : p[1]) + __shfl_xor_sync(FULL, t1, 16);
            r2 = (b4 ? p[6] : p[2]) + __shfl_xor_sync(FULL, t2, 16);
            r3 = (b4 ? p[7] : p[3]) + __shfl_xor_sync(FULL, t3, 16);
        }
        float s0, s1;
        {
            float t0 = b3 ? r0 : r2, t1 = b3 ? r1 : r3;
            s0 = (b3 ? r2 : r0) + __shfl_xor_sync(FULL, t0, 8);
            s1 = (b3 ? r3 : r1) + __shfl_xor_sync(FULL, t1, 8);
        }
        float s;
        {
            float t0 = b2 ? s0 : s1;
            s = (b2 ? s1 : s0) + __shfl_xor_sync(FULL, t0, 4);
        }
        s += __shfl_xor_sync(FULL, s, 2);
        s += __shfl_xor_sync(FULL, s, 1);

        float ex = __expf(s + ch);
        float wh = ex * phi;
        ssum += ex; tsum += wh;

        #pragma unroll
        for (int h = 0; h < 8; h++) {
            float whh = __shfl_sync(FULL, wh, 4 * h);
            U[h].x = fmaf(whh, ac.x, U[h].x);
            U[h].y = fmaf(whh, ac.y, U[h].y);
            U[h].z = fmaf(whh, ac.z, U[h].z);
            U[h].w = fmaf(whh, ac.w, U[h].w);
        }
    }

    float invm = (ssum > 0.f) ? (1.f / ssum) : 0.f;
    if ((l & 3) == 0) sT[w][l >> 2] = tsum * invm;
    #pragma unroll
    for (int h = 0; h < 8; h++) {
        float ivh = __shfl_sync(FULL, invm, 4 * h);
        float4 v = make_float4(U[h].x * ivh, U[h].y * ivh, U[h].z * ivh, U[h].w * ivh);
        reinterpret_cast<float4*>(&sU[w][h][0])[l] = v;
    }
    __syncthreads();

    int c = tid, h = c >> 4;
    {
        float bv = bV[c];
        float a0c = sT[0][h] * bv, a1c = sT[1][h] * bv;
        float a2c = sT[2][h] * bv, a3c = sT[3][h] * bv;
        const float4* u0 = reinterpret_cast<const float4*>(&sU[0][h][0]);
        const float4* u1 = reinterpret_cast<const float4*>(&sU[1][h][0]);
        const float4* u2 = reinterpret_cast<const float4*>(&sU[2][h][0]);
        const float4* u3 = reinterpret_cast<const float4*>(&sU[3][h][0]);
        #pragma unroll 8
        for (int d4 = 0; d4 < 32; d4++) {
            float w0 = WV[(4 * d4 + 0) * DIM + c];
            float w1 = WV[(4 * d4 + 1) * DIM + c];
            float w2 = WV[(4 * d4 + 2) * DIM + c];
            float w3 = WV[(4 * d4 + 3) * DIM + c];
            float4 v;
            v = u0[d4]; a0c = fmaf(v.x, w0, fmaf(v.y, w1, fmaf(v.z, w2, fmaf(v.w, w3, a0c))));
            v = u1[d4]; a1c = fmaf(v.x, w0, fmaf(v.y, w1, fmaf(v.z, w2, fmaf(v.w, w3, a1c))));
            v = u2[d4]; a2c = fmaf(v.x, w0, fmaf(v.y, w1, fmaf(v.z, w2, fmaf(v.w, w3, a2c))));
            v = u3[d4]; a3c = fmaf(v.x, w0, fmaf(v.y, w1, fmaf(v.z, w2, fmaf(v.w, w3, a3c))));
        }
        sno[0][c] = a0c; sno[1][c] = a1c; sno[2][c] = a2c; sno[3][c] = a3c;
    }
    __syncthreads();

    {
        float bo = bO[c];
        float o0 = bo, o1 = bo, o2 = bo, o3 = bo;
        const float4* v0 = reinterpret_cast<const float4*>(&sno[0][0]);
        const float4* v1 = reinterpret_cast<const float4*>(&sno[1][0]);
        const float4* v2 = reinterpret_cast<const float4*>(&sno[2][0]);
        const float4* v3 = reinterpret_cast<const float4*>(&sno[3][0]);
        #pragma unroll 8
        for (int d4 = 0; d4 < 32; d4++) {
            float w0 = WO[(4 * d4 + 0) * DIM + c];
            float w1 = WO[(4 * d4 + 1) * DIM + c];
            float w2 = WO[(4 * d4 + 2) * DIM + c];
            float w3 = WO[(4 * d4 + 3) * DIM + c];
            float4 v;
            v = v0[d4]; o0 = fmaf(v.x, w0, fmaf(v.y, w1, fmaf(v.z, w2, fmaf(v.w, w3, o0))));
            v = v1[d4]; o1 = fmaf(v.x, w0, fmaf(v.y, w1, fmaf(v.z, w2, fmaf(v.w, w3, o1))));
            v = v2[d4]; o2 = fmaf(v.x, w0, fmaf(v.y, w1, fmaf(v.z, w2, fmaf(v.w, w3, o2))));
            v = v3[d4]; o3 = fmaf(v.x, w0, fmaf(v.y, w1, fmaf(v.z, w2, fmaf(v.w, w3, o3))));
        }
        size_t base = (size_t)blockIdx.x * 4;
        out[(base + 0) * DIM + c] = o0;
        out[(base + 1) * DIM + c] = o1;
        out[(base + 2) * DIM + c] = o2;
        out[(base + 3) * DIM + c] = o3;
    }
}

extern "C" void kernel_launch(void* const* d_in, const int* in_sizes, int n_in,
                              void* d_out, int out_size) {
    const float* x    = (const float*)d_in[0];
    const int*   ei   = (const int*)  d_in[1];
    const float* ea   = (const float*)d_in[2];
    const float* elen = (const float*)d_in[3];
    const float* WQ   = (const float*)d_in[4];
    const float* bQ   = (const float*)d_in[5];
    const float* WK   = (const float*)d_in[6];
    const float* bK   = (const float*)d_in[7];
    const float* WV   = (const float*)d_in[8];
    const float* bV   = (const float*)d_in[9];
    const float* WO   = (const float*)d_in[10];
    const float* bO   = (const float*)d_in[11];
    float* out = (float*)d_out;

    static cudaStream_t s2 = nullptr;
    static cudaEvent_t evFork = nullptr, evJoin = nullptr;
    static bool init_done = false;
    if (!init_done) {
        cudaFuncSetAttribute(k_qp, cudaFuncAttributeMaxDynamicSharedMemorySize, QP_SMEM);
        cudaStreamCreateWithFlags(&s2, cudaStreamNonBlocking);
        cudaEventCreateWithFlags(&evFork, cudaEventDisableTiming);
        cudaEventCreateWithFlags(&evJoin, cudaEventDisableTiming);
        init_done = true;
    }

    // fork: q/P chain runs on s2, concurrent with the CSR chain on the main stream
    cudaEventRecord(evFork, 0);
    cudaStreamWaitEvent(s2, evFork, 0);
    k_wkt<<<(DIM * DIM + 255) / 256, 256, 0, s2>>>(WK);
    k_qp<<<(N_NODES + QNB - 1) / QNB, 128, QP_SMEM, s2>>>(x, WQ, bQ, bK);
    cudaEventRecord(evJoin, s2);

    // CSR chain on the main stream
    k_zero<<<(N_NODES + 255) / 256, 256>>>();
    k_hist<<<(N_EDGES + 255) / 256, 256>>>(ei);
    k_scan<<<1, 1024>>>();
    k_scatter<<<(N_EDGES + 255) / 256, 256>>>(ei, elen);

    // join, then fused edge pass
    cudaStreamWaitEvent(0, evJoin, 0);
    k_edge<<<N_NODES / 4, 128>>>((const float4*)ea, WV, bV, WO, bO, out);
}

// round 17
// speedup vs baseline: 1.1966x; 1.0271x over previous
#include <cuda_runtime.h>
#include <cuda_fp16.h>
#include <stdint.h>

#define N_NODES 50000
#define N_EDGES 800000
#define DIM 128
#define KPI 0.62831853071795865f
#define FULL 0xffffffffu
#define QNB 32
#define QPITCH 136
#define QP_SMEM ((128 * QPITCH + 2 * QNB * QPITCH) * 4)

// ---- scratch ----
__device__ __half2 g_Ph[(size_t)N_NODES * 512];  // [n][h][64xhalf2], pre-scaled by 0.25
__device__ float g_c[N_NODES * 8];               // (q.b_K)*0.25
__device__ float g_WKT[DIM * DIM];
__device__ int   g_counts[N_NODES];
__device__ int   g_offsets[N_NODES + 1];
__device__ int   g_cursor[N_NODES];
__device__ int2  g_pe[N_EDGES];                  // (edge, phi bits) CSR order

__device__ __forceinline__ uint32_t f2tf(float f) {
    uint32_t o;
    asm("cvt.rna.tf32.f32 %0, %1;" : "=r"(o) : "f"(f));
    return o;
}
__device__ __forceinline__ void mma_tf32(float c[4], uint32_t a0, uint32_t a1,
                                         uint32_t a2, uint32_t a3,
                                         uint32_t b0, uint32_t b1) {
    asm volatile(
        "mma.sync.aligned.m16n8k8.row.col.f32.tf32.tf32.f32 "
        "{%0,%1,%2,%3}, {%4,%5,%6,%7}, {%8,%9}, {%0,%1,%2,%3};"
        : "+f"(c[0]), "+f"(c[1]), "+f"(c[2]), "+f"(c[3])
        : "r"(a0), "r"(a1), "r"(a2), "r"(a3), "r"(b0), "r"(b1));
}
__device__ __forceinline__ void cpa16(void* dst, const void* src) {
    uint32_t d = (uint32_t)__cvta_generic_to_shared(dst);
    asm volatile("cp.async.cg.shared.global [%0], [%1], 16;" :: "r"(d), "l"(src));
}
__device__ __forceinline__ void cpcommit() {
    asm volatile("cp.async.commit_group;" ::: "memory");
}
template <int N>
__device__ __forceinline__ void cpwait() {
    asm volatile("cp.async.wait_group %0;" :: "n"(N) : "memory");
}

// ---- CSR build ----
__global__ void k_zero() {
    int i = blockIdx.x * blockDim.x + threadIdx.x;
    if (i < N_NODES) g_counts[i] = 0;
}
__global__ void k_hist(const int* __restrict__ ei) {
    int e = blockIdx.x * blockDim.x + threadIdx.x;
    if (e < N_EDGES) atomicAdd(&g_counts[ei[N_EDGES + e]], 1);
}
__global__ void k_scan() {
    __shared__ int wsum[32];
    int t = threadIdx.x, lane = t & 31, wid = t >> 5;
    int carry = 0;
    for (int base = 0; base < N_NODES; base += 1024) {
        int i = base + t;
        int v = (i < N_NODES) ? g_counts[i] : 0;
        int x = v;
        #pragma unroll
        for (int o = 1; o < 32; o <<= 1) { int y = __shfl_up_sync(FULL, x, o); if (lane >= o) x += y; }
        if (lane == 31) wsum[wid] = x;
        __syncthreads();
        if (wid == 0) {
            int s = wsum[lane];
            #pragma unroll
            for (int o = 1; o < 32; o <<= 1) { int y = __shfl_up_sync(FULL, s, o); if (lane >= o) s += y; }
            wsum[lane] = s;
        }
        __syncthreads();
        int excl = x - v + (wid ? wsum[wid - 1] : 0);
        if (i < N_NODES) { g_offsets[i] = carry + excl; g_cursor[i] = carry + excl; }
        carry += wsum[31];
        __syncthreads();
    }
    if (t == 0) g_offsets[N_NODES] = carry;
}
__global__ void k_scatter(const int* __restrict__ ei, const float* __restrict__ elen) {
    int e = blockIdx.x * blockDim.x + threadIdx.x;
    if (e < N_EDGES) {
        int j = ei[N_EDGES + e];
        int pos = atomicAdd(&g_cursor[j], 1);
        float phi = fmaf(0.5f, __cosf(elen[e] * KPI), 0.5f);
        g_pe[pos] = make_int2(e, __float_as_int(phi));
    }
}
__global__ void k_wkt(const float* __restrict__ WK) {
    int i = blockIdx.x * blockDim.x + threadIdx.x;
    if (i < DIM * DIM) g_WKT[(i % DIM) * DIM + (i / DIM)] = WK[i];
}

// ---- node precompute on tensor cores (tf32): q = xWQ+bQ; P_h = q_h @ WKT_h ----
__global__ void __launch_bounds__(128) k_qp(
    const float* __restrict__ x, const float* __restrict__ WQ,
    const float* __restrict__ bQ, const float* __restrict__ bK)
{
    extern __shared__ uint32_t sm[];
    uint32_t* s_w = sm;
    uint32_t* s_x = sm + 128 * QPITCH;
    uint32_t* s_q = s_x + QNB * QPITCH;
    int tid = threadIdx.x, lane = tid & 31, wp = tid >> 5;
    int g = lane >> 2, tg = lane & 3;
    int nb0 = blockIdx.x * QNB;
    int wbase = wp * 32;

    #pragma unroll
    for (int it = 0; it < 8; it++) {
        int idx = tid + it * 128;
        int row = idx >> 5, c4 = (idx & 31) * 4;
        int node = nb0 + row;
        float4 v = make_float4(0.f, 0.f, 0.f, 0.f);
        if (node < N_NODES) v = *reinterpret_cast<const float4*>(x + (size_t)node * DIM + c4);
        s_x[row * QPITCH + c4 + 0] = f2tf(v.x);
        s_x[row * QPITCH + c4 + 1] = f2tf(v.y);
        s_x[row * QPITCH + c4 + 2] = f2tf(v.z);
        s_x[row * QPITCH + c4 + 3] = f2tf(v.w);
    }
    #pragma unroll 8
    for (int it = 0; it < 32; it++) {
        int idx = tid + it * 128;
        int row = idx >> 5, c4 = (idx & 31) * 4;
        float4 v = *reinterpret_cast<const float4*>(WQ + row * DIM + c4);
        s_w[row * QPITCH + c4 + 0] = f2tf(v.x);
        s_w[row * QPITCH + c4 + 1] = f2tf(v.y);
        s_w[row * QPITCH + c4 + 2] = f2tf(v.z);
        s_w[row * QPITCH + c4 + 3] = f2tf(v.w);
    }
    __syncthreads();

    #pragma unroll
    for (int mt = 0; mt < 2; mt++) {
        float c[4][4];
        #pragma unroll
        for (int nt = 0; nt < 4; nt++) {
            int col = wbase + nt * 8 + 2 * tg;
            c[nt][0] = bQ[col]; c[nt][1] = bQ[col + 1];
            c[nt][2] = c[nt][0]; c[nt][3] = c[nt][1];
        }
        #pragma unroll
        for (int kt = 0; kt < 16; kt++) {
            int ra = (mt * 16 + g) * QPITCH + kt * 8 + tg;
            int rb = (mt * 16 + g + 8) * QPITCH + kt * 8 + tg;
            uint32_t a0 = s_x[ra], a1 = s_x[rb], a2 = s_x[ra + 4], a3 = s_x[rb + 4];
            #pragma unroll
            for (int nt = 0; nt < 4; nt++) {
                int cb = wbase + nt * 8 + g;
                uint32_t b0 = s_w[(kt * 8 + tg) * QPITCH + cb];
                uint32_t b1 = s_w[(kt * 8 + tg + 4) * QPITCH + cb];
                mma_tf32(c[nt], a0, a1, a2, a3, b0, b1);
            }
        }
        #pragma unroll
        for (int nt = 0; nt < 4; nt++) {
            int col = wbase + nt * 8 + 2 * tg;
            s_q[(mt * 16 + g) * QPITCH + col]         = f2tf(c[nt][0]);
            s_q[(mt * 16 + g) * QPITCH + col + 1]     = f2tf(c[nt][1]);
            s_q[(mt * 16 + g + 8) * QPITCH + col]     = f2tf(c[nt][2]);
            s_q[(mt * 16 + g + 8) * QPITCH + col + 1] = f2tf(c[nt][3]);
        }
    }
    __syncthreads();

    #pragma unroll 8
    for (int it = 0; it < 32; it++) {
        int idx = tid + it * 128;
        int row = idx >> 5, c4 = (idx & 31) * 4;
        float4 v = *reinterpret_cast<const float4*>(g_WKT + row * DIM + c4);
        s_w[row * QPITCH + c4 + 0] = f2tf(v.x);
        s_w[row * QPITCH + c4 + 1] = f2tf(v.y);
        s_w[row * QPITCH + c4 + 2] = f2tf(v.z);
        s_w[row * QPITCH + c4 + 3] = f2tf(v.w);
    }
    #pragma unroll
    for (int it = 0; it < 2; it++) {
        int item = tid + it * 128;
        int i = item >> 3, h = item & 7;
        int node = nb0 + i;
        if (node < N_NODES) {
            float cc = 0.f;
            #pragma unroll
            for (int k = 0; k < 16; k++)
                cc = fmaf(__uint_as_float(s_q[i * QPITCH + h * 16 + k]), bK[h * 16 + k], cc);
            g_c[node * 8 + h] = cc * 0.25f;
        }
    }
    __syncthreads();

    #pragma unroll
    for (int mt = 0; mt < 2; mt++) {
        int node0 = nb0 + mt * 16 + g, node1 = node0 + 8;
        #pragma unroll
        for (int h = 0; h < 8; h++) {
            float c[4][4];
            #pragma unroll
            for (int nt = 0; nt < 4; nt++)
                c[nt][0] = c[nt][1] = c[nt][2] = c[nt][3] = 0.f;
            #pragma unroll
            for (int kt = 0; kt < 2; kt++) {
                int qa = (mt * 16 + g) * QPITCH + h * 16 + kt * 8 + tg;
                int qb = (mt * 16 + g + 8) * QPITCH + h * 16 + kt * 8 + tg;
                uint32_t a0 = s_q[qa], a1 = s_q[qb], a2 = s_q[qa + 4], a3 = s_q[qb + 4];
                #pragma unroll
                for (int nt = 0; nt < 4; nt++) {
                    int cb = wbase + nt * 8 + g;
                    uint32_t b0 = s_w[(h * 16 + kt * 8 + tg) * QPITCH + cb];
                    uint32_t b1 = s_w[(h * 16 + kt * 8 + tg + 4) * QPITCH + cb];
                    mma_tf32(c[nt], a0, a1, a2, a3, b0, b1);
                }
            }
            if (node0 < N_NODES) {
                #pragma unroll
                for (int nt = 0; nt < 4; nt++) {
                    int c2 = wp * 16 + nt * 4 + tg;
                    g_Ph[(size_t)node0 * 512 + h * 64 + c2] =
                        __floats2half2_rn(0.25f * c[nt][0], 0.25f * c[nt][1]);
                }
            }
            if (node1 < N_NODES) {
                #pragma unroll
                for (int nt = 0; nt < 4; nt++) {
                    int c2 = wp * 16 + nt * 4 + tg;
                    g_Ph[(size_t)node1 * 512 + h * 64 + c2] =
                        __floats2half2_rn(0.25f * c[nt][2], 0.25f * c[nt][3]);
                }
            }
        }
    }
}

// ---- fused edge pass: cp.async 8-deep row ring (warp=node, 4 nodes/block) ----
__global__ void __launch_bounds__(128, 5) k_edge(
    const float4* __restrict__ ea4,
    const float* __restrict__ WV, const float* __restrict__ bV,
    const float* __restrict__ WO, const float* __restrict__ bO,
    float* __restrict__ out)
{
    __shared__ float4 ring[4][8][32];   // 8-deep async row buffer per warp (16 KB)
    __shared__ float sU[4][8][DIM];
    __shared__ float sT[4][8];
    __shared__ float sno[4][DIM];
    int tid = threadIdx.x, w = tid >> 5, l = tid & 31;
    int n = blockIdx.x * 4 + w;

    float4 P4[8];
    {
        const uint2* gp = reinterpret_cast<const uint2*>(g_Ph + (size_t)n * 512);
        #pragma unroll
        for (int h = 0; h < 8; h++) {
            uint2 v = gp[h * 32 + l];
            float2 f01 = __half22float2(*reinterpret_cast<__half2*>(&v.x));
            float2 f23 = __half22float2(*reinterpret_cast<__half2*>(&v.y));
            P4[h] = make_float4(f01.x, f01.y, f23.x, f23.y);
        }
    }
    float ch = g_c[n * 8 + (l >> 2)];

    float4 U[8];
    #pragma unroll
    for (int h = 0; h < 8; h++) U[h] = make_float4(0.f, 0.f, 0.f, 0.f);
    float ssum = 0.f, tsum = 0.f;
    bool b4 = (l & 16), b3 = (l & 8), b2 = (l & 4);

    int beg = g_offsets[n], end = g_offsets[n + 1];
    int deg = end - beg;

    // pe chunks: lane l holds pe of edge beg+co+l (cur) / beg+co+32+l (nxt)
    int2 pe_cur = make_int2(0, 0), pe_nxt = make_int2(0, 0);
    if (beg + l < end)      pe_cur = g_pe[beg + l];
    if (beg + 32 + l < end) pe_nxt = g_pe[beg + 32 + l];
    int co = 0;

    // prologue: fill the 8-deep ring
    #pragma unroll
    for (int d = 0; d < 8; d++) {
        int row = __shfl_sync(FULL, pe_cur.x, d);   // pe_cur.x = 0 for d >= deg
        if (d >= deg) row = 0;
        cpa16(&ring[w][d][l], ea4 + (size_t)row * 32 + l);
        cpcommit();
    }

    for (int k = 0; k < deg; k++) {
        int kc = k - co;
        if (kc == 32) {
            pe_cur = pe_nxt; co += 32; kc = 0;
            pe_nxt = make_int2(0, 0);
            if (beg + co + 32 + l < end) pe_nxt = g_pe[beg + co + 32 + l];
        }
        float phi = __int_as_float(__shfl_sync(FULL, pe_cur.y, kc));

        int slot = k & 7;
        cpwait<7>();                       // oldest ring slot ready (per-lane own data)
        float4 ac = ring[w][slot][l];

        // refill slot with edge k+8
        int kn = k + 8;
        if (kn < deg) {
            int knc = kn - co;
            int row = (knc < 32) ? __shfl_sync(FULL, pe_cur.x, knc)
                                 : __shfl_sync(FULL, pe_nxt.x, knc - 32);
            cpa16(&ring[w][slot][l], ea4 + (size_t)row * 32 + l);
        }
        cpcommit();                        // empty group on tail keeps invariant

        float p[8];
        #pragma unroll
        for (int h = 0; h < 8; h++)
            p[h] = fmaf(ac.x, P4[h].x, fmaf(ac.y, P4[h].y, fmaf(ac.z, P4[h].z, ac.w * P4[h].w)));

        float r0, r1, r2, r3;
        {
            float t0 = b4 ? p[0] : p[4], t1 = b4 ? p[1] : p[5];
            float t2 = b4 ? p[2] : p[6], t3 = b4 ? p[3] : p[7];
            r0 = (b4 ? p[4] : p[0]) + __shfl_xor_sync(FULL, t0, 16);
            r1 = (b4 ? p[5] : p[1]) + __shfl_xor_sync(FULL, t1, 16);
            r2 = (b4 ? p[6] : p[2]) + __shfl_xor_sync(FULL, t2, 16);
            r3 = (b4 ? p[7] : p[3]) + __shfl_xor_sync(FULL, t3, 16);
        }
        float s0, s1;
        {
            float t0 = b3 ? r0 : r2, t1 = b3 ? r1 : r3;
            s0 = (b3 ? r2 : r0) + __shfl_xor_sync(FULL, t0, 8);
            s1 = (b3 ? r3 : r1) + __shfl_xor_sync(FULL, t1, 8);
        }
        float s;
        {
            float t0 = b2 ? s0 : s1;
            s = (b2 ? s1 : s0) + __shfl_xor_sync(FULL, t0, 4);
        }
        s += __shfl_xor_sync(FULL, s, 2);
        s += __shfl_xor_sync(FULL, s, 1);

        float ex = __expf(s + ch);
        float wh = ex * phi;
        ssum += ex; tsum += wh;

        #pragma unroll
        for (int h = 0; h < 8; h++) {
            float whh = __shfl_sync(FULL, wh, 4 * h);
            U[h].x = fmaf(whh, ac.x, U[h].x);
            U[h].y = fmaf(whh, ac.y, U[h].y);
            U[h].z = fmaf(whh, ac.z, U[h].z);
            U[h].w = fmaf(whh, ac.w, U[h].w);
        }
    }
    cpwait<0>();   // drain pending ring writes before smem reuse boundary

    float invm = (ssum > 0.f) ? (1.f / ssum) : 0.f;
    if ((l & 3) == 0) sT[w][l >> 2] = tsum * invm;
    #pragma unroll
    for (int h = 0; h < 8; h++) {
        float ivh = __shfl_sync(FULL, invm, 4 * h);
        float4 v = make_float4(U[h].x * ivh, U[h].y * ivh, U[h].z * ivh, U[h].w * ivh);
        reinterpret_cast<float4*>(&sU[w][h][0])[l] = v;
    }
    __syncthreads();

    int c = tid, h = c >> 4;
    {
        float bv = bV[c];
        float a0c = sT[0][h] * bv, a1c = sT[1][h] * bv;
        float a2c = sT[2][h] * bv, a3c = sT[3][h] * bv;
        const float4* u0 = reinterpret_cast<const float4*>(&sU[0][h][0]);
        const float4* u1 = reinterpret_cast<const float4*>(&sU[1][h][0]);
        const float4* u2 = reinterpret_cast<const float4*>(&sU[2][h][0]);
        const float4* u3 = reinterpret_cast<const float4*>(&sU[3][h][0]);
        #pragma unroll 8
        for (int d4 = 0; d4 < 32; d4++) {
            float w0 = WV[(4 * d4 + 0) * DIM + c];
            float w1 = WV[(4 * d4 + 1) * DIM + c];
            float w2 = WV[(4 * d4 + 2) * DIM + c];
            float w3 = WV[(4 * d4 + 3) * DIM + c];
            float4 v;
            v = u0[d4]; a0c = fmaf(v.x, w0, fmaf(v.y, w1, fmaf(v.z, w2, fmaf(v.w, w3, a0c))));
            v = u1[d4]; a1c = fmaf(v.x, w0, fmaf(v.y, w1, fmaf(v.z, w2, fmaf(v.w, w3, a1c))));
            v = u2[d4]; a2c = fmaf(v.x, w0, fmaf(v.y, w1, fmaf(v.z, w2, fmaf(v.w, w3, a2c))));
            v = u3[d4]; a3c = fmaf(v.x, w0, fmaf(v.y, w1, fmaf(v.z, w2, fmaf(v.w, w3, a3c))));
        }
        sno[0][c] = a0c; sno[1][c] = a1c; sno[2][c] = a2c; sno[3][c] = a3c;
    }
    __syncthreads();

    {
        float bo = bO[c];
        float o0 = bo, o1 = bo, o2 = bo, o3 = bo;
        const float4* v0 = reinterpret_cast<const float4*>(&sno[0][0]);
        const float4* v1 = reinterpret_cast<const float4*>(&sno[1][0]);
        const float4* v2 = reinterpret_cast<const float4*>(&sno[2][0]);
        const float4* v3 = reinterpret_cast<const float4*>(&sno[3][0]);
        #pragma unroll 8
        for (int d4 = 0; d4 < 32; d4++) {
            float w0 = WO[(4 * d4 + 0) * DIM + c];
            float w1 = WO[(4 * d4 + 1) * DIM + c];
            float w2 = WO[(4 * d4 + 2) * DIM + c];
            float w3 = WO[(4 * d4 + 3) * DIM + c];
            float4 v;
            v = v0[d4]; o0 = fmaf(v.x, w0, fmaf(v.y, w1, fmaf(v.z, w2, fmaf(v.w, w3, o0))));
            v = v1[d4]; o1 = fmaf(v.x, w0, fmaf(v.y, w1, fmaf(v.z, w2, fmaf(v.w, w3, o1))));
            v = v2[d4]; o2 = fmaf(v.x, w0, fmaf(v.y, w1, fmaf(v.z, w2, fmaf(v.w, w3, o2))));
            v = v3[d4]; o3 = fmaf(v.x, w0, fmaf(v.y, w1, fmaf(v.z, w2, fmaf(v.w, w3, o3))));
        }
        size_t base = (size_t)blockIdx.x * 4;
        out[(base + 0) * DIM + c] = o0;
        out[(base + 1) * DIM + c] = o1;
        out[(base + 2) * DIM + c] = o2;
        out[(base + 3) * DIM + c] = o3;
    }
}

extern "C" void kernel_launch(void* const* d_in, const int* in_sizes, int n_in,
                              void* d_out, int out_size) {
    const float* x    = (const float*)d_in[0];
    const int*   ei   = (const int*)  d_in[1];
    const float* ea   = (const float*)d_in[2];
    const float* elen = (const float*)d_in[3];
    const float* WQ   = (const float*)d_in[4];
    const float* bQ   = (const float*)d_in[5];
    const float* WK   = (const float*)d_in[6];
    const float* bK   = (const float*)d_in[7];
    const float* WV   = (const float*)d_in[8];
    const float* bV   = (const float*)d_in[9];
    const float* WO   = (const float*)d_in[10];
    const float* bO   = (const float*)d_in[11];
    float* out = (float*)d_out;

    static cudaStream_t s2 = nullptr;
    static cudaEvent_t evFork = nullptr, evJoin = nullptr;
    static bool init_done = false;
    if (!init_done) {
        cudaFuncSetAttribute(k_qp, cudaFuncAttributeMaxDynamicSharedMemorySize, QP_SMEM);
        cudaStreamCreateWithFlags(&s2, cudaStreamNonBlocking);
        cudaEventCreateWithFlags(&evFork, cudaEventDisableTiming);
        cudaEventCreateWithFlags(&evJoin, cudaEventDisableTiming);
        init_done = true;
    }

    // fork: q/P chain runs on s2, concurrent with the CSR chain on the main stream
    cudaEventRecord(evFork, 0);
    cudaStreamWaitEvent(s2, evFork, 0);
    k_wkt<<<(DIM * DIM + 255) / 256, 256, 0, s2>>>(WK);
    k_qp<<<(N_NODES + QNB - 1) / QNB, 128, QP_SMEM, s2>>>(x, WQ, bQ, bK);
    cudaEventRecord(evJoin, s2);

    // CSR chain on the main stream
    k_zero<<<(N_NODES + 255) / 256, 256>>>();
    k_hist<<<(N_EDGES + 255) / 256, 256>>>(ei);
    k_scan<<<1, 1024>>>();
    k_scatter<<<(N_EDGES + 255) / 256, 256>>>(ei, elen);

    // join, then fused edge pass
    cudaStreamWaitEvent(0, evJoin, 0);
    k_edge<<<N_NODES / 4, 128>>>((const float4*)ea, WV, bV, WO, bO, out);
}